// round 9
// baseline (speedup 1.0000x reference)
#include <cuda_runtime.h>
#include <cuda_bf16.h>
#include <cstdint>

// Problem constants: z_e (16,4096,64) f32, embed (1024,64) f32.
#define N_ROWS  65536
#define DIM     64
#define KCODES  1024
#define M_CTA   128
#define NT      64
#define NTILES  (KCODES / NT)      // 16
#define THREADS 256
#define NBLOCKS (N_ROWS / M_CTA)   // 512
#define NCAND   24
#define WCOEF   0.0171875f         // 2 * 1.1 * 2^-7 (Cauchy-Schwarz bf16 bound)

// smem byte offsets
#define SM_HNE    0         // 1024 f32 = 4096
#define SM_XHI    4096      // 128x128B swizzled bf16 = 16384
#define SM_B      20480     // 4 bufs x 8192 = 32768
#define SM_BUF    53248     // 128*24 u32 = 12288
#define SM_CNT    65536     // 128 i32
#define SM_BEST   66048     // 128 u64 = 1024
#define SM_NX     67072     // 128 f32
#define SM_RLIST  67584     // 128 i32
#define SM_NRES   68096     // i32 (+pad)
#define SM_ROWIDX 68112     // 128 i32
#define SM_RED    68624     // 256 f32
#define SM_RI     69648     // 256 i32
#define SMEM_BYTES 70672

__device__ float g_hne[KCODES];        // -0.5 * ||e_k||^2
__device__ float g_partial[NBLOCKS];
__device__ uint4 g_ehi4[KCODES * 8];   // E hi bf16, 8 x uint4 per code (128B/code)
__device__ int   g_emax2i = 0;         // bits of max ||e||^2 (positive floats)

// ===================== helpers =====================
__device__ __forceinline__ uint32_t smem_to_u32(const void* p) {
    uint32_t a;
    asm("{ .reg .u64 t; cvta.to.shared.u64 t, %1; cvt.u32.u64 %0, t; }"
        : "=r"(a) : "l"(p));
    return a;
}
__device__ __forceinline__ uint32_t bf2hi(float a, float b) {
    return (uint32_t)__bfloat16_as_ushort(__float2bfloat16_rn(a)) |
           ((uint32_t)__bfloat16_as_ushort(__float2bfloat16_rn(b)) << 16);
}
__device__ __forceinline__ uint32_t fkey(float f) {
    uint32_t u = __float_as_uint(f);
    return (u & 0x80000000u) ? ~u : (u | 0x80000000u);
}

#define LDSM4(r, addr) \
    asm volatile("ldmatrix.sync.aligned.m8n8.x4.shared.b16 {%0,%1,%2,%3}, [%4];" \
        : "=r"((r)[0]), "=r"((r)[1]), "=r"((r)[2]), "=r"((r)[3]) : "r"(addr))

#define MMA16816(d, a, b0_, b1_) \
    asm volatile("mma.sync.aligned.m16n8k16.row.col.f32.bf16.bf16.f32 " \
        "{%0,%1,%2,%3}, {%4,%5,%6,%7}, {%8,%9}, {%0,%1,%2,%3};" \
        : "+f"((d)[0]), "+f"((d)[1]), "+f"((d)[2]), "+f"((d)[3]) \
        : "r"((a)[0]), "r"((a)[1]), "r"((a)[2]), "r"((a)[3]), "r"(b0_), "r"(b1_))

#define CP_ASYNC16(dst, src) \
    asm volatile("cp.async.cg.shared.global [%0], [%1], 16;" \
        :: "r"(dst), "l"(src) : "memory")
#define CP_COMMIT() asm volatile("cp.async.commit_group;" ::: "memory")
#define CP_WAIT2()  asm volatile("cp.async.wait_group 2;" ::: "memory")

// ===================== kernel 0: dummy (ncu alignment) ====================
__global__ void vq_dummy_kernel() {}

// ===================== kernel 1: prep =====================
__global__ void vq_prep_kernel(const float* __restrict__ embed) {
    const int g = blockIdx.x * blockDim.x + threadIdx.x;   // 0..4095
    const int code = g >> 2, q = g & 3;
    const float4* e4 = reinterpret_cast<const float4*>(
        embed + (size_t)code * DIM + q * 16);
    float4 v0 = e4[0], v1 = e4[1], v2 = e4[2], v3 = e4[3];
    float s = v0.x*v0.x + v0.y*v0.y + v0.z*v0.z + v0.w*v0.w
            + v1.x*v1.x + v1.y*v1.y + v1.z*v1.z + v1.w*v1.w
            + v2.x*v2.x + v2.y*v2.y + v2.z*v2.z + v2.w*v2.w
            + v3.x*v3.x + v3.y*v3.y + v3.z*v3.z + v3.w*v3.w;
    g_ehi4[code * 8 + q * 2] =
        make_uint4(bf2hi(v0.x, v0.y), bf2hi(v0.z, v0.w),
                   bf2hi(v1.x, v1.y), bf2hi(v1.z, v1.w));
    g_ehi4[code * 8 + q * 2 + 1] =
        make_uint4(bf2hi(v2.x, v2.y), bf2hi(v2.z, v2.w),
                   bf2hi(v3.x, v3.y), bf2hi(v3.z, v3.w));
    s += __shfl_xor_sync(0xffffffffu, s, 1);
    s += __shfl_xor_sync(0xffffffffu, s, 2);
    if (q == 0) {
        g_hne[code] = -0.5f * s;
        atomicMax(&g_emax2i, __float_as_int(s));   // idempotent, deterministic
    }
}

// ===================== kernel 2: main =====================
__device__ __forceinline__ void stage_tile(uint32_t smem_base, int buf, int t, int tid) {
    const char* g = reinterpret_cast<const char*>(g_ehi4);
#pragma unroll
    for (int cc = 0; cc < 2; ++cc) {
        int c = tid * 2 + cc;                              // 0..511
        uint32_t rowb = (uint32_t)(c >> 3) * 128u;
        uint32_t col  = ((uint32_t)(c & 7) * 16u) ^ ((((uint32_t)c >> 3) & 7u) << 4);
        uint32_t dst = smem_base + SM_B + (uint32_t)buf * 8192u + rowb + col;
        CP_ASYNC16(dst, g + ((size_t)t * 512 + c) * 16);
    }
}

__global__ __launch_bounds__(THREADS, 3)
void vq_main_kernel(const float* __restrict__ z_e,
                    const float* __restrict__ embed,
                    float* __restrict__ out) {
    extern __shared__ char smem[];
    const uint32_t smem_base = smem_to_u32(smem);
    const int tid  = threadIdx.x;
    const int lane = tid & 31;
    const int wid  = tid >> 5;
    const int row0 = blockIdx.x * M_CTA;

    float*     s_hne    = reinterpret_cast<float*>(smem + SM_HNE);
    uint32_t*  s_buf    = reinterpret_cast<uint32_t*>(smem + SM_BUF);
    int*       s_cnt    = reinterpret_cast<int*>(smem + SM_CNT);
    unsigned long long* s_best =
        reinterpret_cast<unsigned long long*>(smem + SM_BEST);
    float*     s_nx     = reinterpret_cast<float*>(smem + SM_NX);
    int*       s_rlist  = reinterpret_cast<int*>(smem + SM_RLIST);
    int*       s_nres   = reinterpret_cast<int*>(smem + SM_NRES);
    int*       s_rowidx = reinterpret_cast<int*>(smem + SM_ROWIDX);
    float*     s_rm     = reinterpret_cast<float*>(smem + SM_RED);
    int*       s_ri     = reinterpret_cast<int*>(smem + SM_RI);

    // Prologue: stage tiles 0,1,2 into ring bufs 0,1,2.
    stage_tile(smem_base, 0, 0, tid); CP_COMMIT();
    stage_tile(smem_base, 1, 1, tid); CP_COMMIT();
    stage_tile(smem_base, 2, 2, tid); CP_COMMIT();

    if (tid < M_CTA) { s_cnt[tid] = 0; s_best[tid] = 0ull; }
    if (tid == 0) *s_nres = 0;

    // ---- stage X: row norms + bf16-hi swizzled tile (no fp32 smem copy) ----
#pragma unroll
    for (int it = 0; it < 2; ++it) {
        const int xrow = it * 64 + (tid >> 2), q = tid & 3;
        const float4* xs = reinterpret_cast<const float4*>(
            z_e + (size_t)(row0 + xrow) * DIM + q * 16);
        float4 v0 = xs[0], v1 = xs[1], v2 = xs[2], v3 = xs[3];
        float nx = v0.x*v0.x + v0.y*v0.y + v0.z*v0.z + v0.w*v0.w
                 + v1.x*v1.x + v1.y*v1.y + v1.z*v1.z + v1.w*v1.w
                 + v2.x*v2.x + v2.y*v2.y + v2.z*v2.z + v2.w*v2.w
                 + v3.x*v3.x + v3.y*v3.y + v3.z*v3.z + v3.w*v3.w;
        nx += __shfl_xor_sync(0xffffffffu, nx, 1);
        nx += __shfl_xor_sync(0xffffffffu, nx, 2);
        if (q == 0) s_nx[xrow] = nx;
        const uint32_t xo = ((uint32_t)(xrow & 7)) << 4;
        *reinterpret_cast<uint4*>(smem + SM_XHI + xrow * 128 +
                                  (((uint32_t)(q * 32)) ^ xo)) =
            make_uint4(bf2hi(v0.x, v0.y), bf2hi(v0.z, v0.w),
                       bf2hi(v1.x, v1.y), bf2hi(v1.z, v1.w));
        *reinterpret_cast<uint4*>(smem + SM_XHI + xrow * 128 +
                                  (((uint32_t)(q * 32 + 16)) ^ xo)) =
            make_uint4(bf2hi(v2.x, v2.y), bf2hi(v2.z, v2.w),
                       bf2hi(v3.x, v3.y), bf2hi(v3.z, v3.w));
    }
#pragma unroll
    for (int i = 0; i < 4; ++i) s_hne[tid + i * 256] = g_hne[tid + i * 256];
    __syncthreads();

    // ---- A fragments (warp wid owns rows wid*16..+15) ----
    uint32_t ah[4][4];
    {
        const uint32_t arow = (uint32_t)(wid * 16 + (lane & 15));
        const uint32_t acs  = (uint32_t)(lane & 16);
        const uint32_t axor = (arow & 7u) << 4;
        const uint32_t ab   = smem_base + SM_XHI + arow * 128u;
#pragma unroll
        for (int kc = 0; kc < 4; ++kc)
            LDSM4(ah[kc], ab + (((uint32_t)(kc * 32) | acs) ^ axor));
    }
    const uint32_t bco  = (uint32_t)((lane & 7) + ((lane & 16) >> 1));
    const uint32_t bcs  = (uint32_t)((lane & 8) << 1);
    const uint32_t bxor = (bco & 7u) << 4;
    const int lq2 = (lane & 3) * 2;
    const int rlo = wid * 16 + (lane >> 2);
    const int rhi = rlo + 8;

    const float emax = sqrtf(__int_as_float(g_emax2i));
    const float w20 = WCOEF * sqrtf(s_nx[rlo]) * emax;
    const float w21 = WCOEF * sqrtf(s_nx[rhi]) * emax;

    float m0 = -3.4e38f, m1 = -3.4e38f;

    // Half-tile MMA: 32 codes (h = 0/1), acc[4][4] live — fits reg budget.
    auto mma_half = [&](int buf, int t, int h, float (&acc)[4][4]) {
        const int cb0 = t * NT + h * 32 + lq2;
#pragma unroll
        for (int nb = 0; nb < 4; ++nb) {
            float2 hn = *reinterpret_cast<const float2*>(&s_hne[cb0 + nb * 8]);
            acc[nb][0] = hn.x; acc[nb][1] = hn.y; acc[nb][2] = hn.x; acc[nb][3] = hn.y;
        }
        const uint32_t bbase = smem_base + SM_B + (uint32_t)buf * 8192u +
                               (uint32_t)h * 4096u + bco * 128u;
#pragma unroll
        for (int kc = 0; kc < 4; ++kc) {
            const uint32_t col = ((uint32_t)(kc * 32) | bcs) ^ bxor;
#pragma unroll
            for (int p = 0; p < 2; ++p) {
                uint32_t bh[4];
                LDSM4(bh, bbase + (uint32_t)(p * 2048) + col);
                MMA16816(acc[2 * p],     ah[kc], bh[0], bh[1]);
                MMA16816(acc[2 * p + 1], ah[kc], bh[2], bh[3]);
            }
        }
    };

    // Threshold/insert for one half-tile (32 codes).
    float thr0, thr1;
    auto score_half = [&](int t, int h, float (&acc)[4][4]) {
        float t0 = fmaxf(fmaxf(fmaxf(acc[0][0], acc[0][1]), fmaxf(acc[1][0], acc[1][1])),
                         fmaxf(fmaxf(acc[2][0], acc[2][1]), fmaxf(acc[3][0], acc[3][1])));
        float t1 = fmaxf(fmaxf(fmaxf(acc[0][2], acc[0][3]), fmaxf(acc[1][2], acc[1][3])),
                         fmaxf(fmaxf(acc[2][2], acc[2][3]), fmaxf(acc[3][2], acc[3][3])));
        // Quad-share: thresholds track true row prefix max (R7 lesson).
        t0 = fmaxf(t0, __shfl_xor_sync(0xffffffffu, t0, 1));
        t0 = fmaxf(t0, __shfl_xor_sync(0xffffffffu, t0, 2));
        t1 = fmaxf(t1, __shfl_xor_sync(0xffffffffu, t1, 1));
        t1 = fmaxf(t1, __shfl_xor_sync(0xffffffffu, t1, 2));

        const int cb0 = t * NT + h * 32 + lq2;
        if (t0 >= thr0) {      // rare slow path
            const float th = fminf(thr0, fmaxf(m0, t0) - w20);
#pragma unroll
            for (int nb = 0; nb < 4; ++nb) {
#pragma unroll
                for (int c = 0; c < 2; ++c) {
                    if (acc[nb][c] >= th) {
                        int pos = atomicAdd(&s_cnt[rlo], 1);
                        if (pos < NCAND)
                            s_buf[rlo * NCAND + pos] = (uint32_t)(cb0 + nb * 8 + c);
                    }
                }
            }
            m0 = fmaxf(m0, t0); thr0 = m0 - w20;
        }
        if (t1 >= thr1) {
            const float th = fminf(thr1, fmaxf(m1, t1) - w21);
#pragma unroll
            for (int nb = 0; nb < 4; ++nb) {
#pragma unroll
                for (int c = 0; c < 2; ++c) {
                    if (acc[nb][c + 2] >= th) {
                        int pos = atomicAdd(&s_cnt[rhi], 1);
                        if (pos < NCAND)
                            s_buf[rhi * NCAND + pos] = (uint32_t)(cb0 + nb * 8 + c);
                    }
                }
            }
            m1 = fmaxf(m1, t1); thr1 = m1 - w21;
        }
    };

    // ---- warmup on tile 0 (max only; tile 0 re-processed with inserts) ----
    {
        float acc[4][4];
        CP_WAIT2(); __syncthreads();
#pragma unroll
        for (int h = 0; h < 2; ++h) {
            mma_half(0, 0, h, acc);
#pragma unroll
            for (int nb = 0; nb < 4; ++nb) {
                m0 = fmaxf(m0, fmaxf(acc[nb][0], acc[nb][1]));
                m1 = fmaxf(m1, fmaxf(acc[nb][2], acc[nb][3]));
            }
        }
        m0 = fmaxf(m0, __shfl_xor_sync(0xffffffffu, m0, 1));
        m0 = fmaxf(m0, __shfl_xor_sync(0xffffffffu, m0, 2));
        m1 = fmaxf(m1, __shfl_xor_sync(0xffffffffu, m1, 1));
        m1 = fmaxf(m1, __shfl_xor_sync(0xffffffffu, m1, 2));
    }
    thr0 = m0 - w20; thr1 = m1 - w21;

    // ---- main loop: 1 sync/tile, two half-passes ----
#pragma unroll 1
    for (int t = 0; t < NTILES; ++t) {
        CP_WAIT2();            // tile t complete (<=2 younger groups pending)
        __syncthreads();       // tile t visible; buffer (t-1)&3 fully consumed
        if (t + 3 < NTILES) stage_tile(smem_base, (t + 3) & 3, t + 3, tid);
        CP_COMMIT();           // empty group when nothing staged: keeps wait math

        float acc[4][4];
        mma_half(t & 3, t, 0, acc);
        score_half(t, 0, acc);
        mma_half(t & 3, t, 1, acc);
        score_half(t, 1, acc);
    }
    __syncthreads();

    // ---- collect overflow rows ----
    if (tid < M_CTA && s_cnt[tid] > NCAND) {
        int p = atomicAdd(s_nres, 1);
        s_rlist[p] = tid;
    }
    __syncthreads();

    // ---- exact fp32 rescore of buffered candidates (2 threads/row) ----
    {
        const int r = tid >> 1;
        const int cr = s_cnt[r];
        if (cr <= NCAND) {
            const float4* x4 = reinterpret_cast<const float4*>(
                z_e + (size_t)(row0 + r) * DIM);
#pragma unroll 1
            for (int c = tid & 1; c < cr; c += 2) {
                const int idx = (int)s_buf[r * NCAND + c];
                const float4* e4 = reinterpret_cast<const float4*>(
                    embed + (size_t)idx * DIM);
                float dot = 0.f;
#pragma unroll
                for (int i = 0; i < 16; ++i) {
                    float4 e = e4[i];
                    float4 x = x4[i];
                    dot += x.x * e.x + x.y * e.y + x.z * e.z + x.w * e.w;
                }
                unsigned long long pk =
                    ((unsigned long long)fkey(dot + s_hne[idx]) << 32) |
                    (unsigned long long)(uint32_t)(1023 - idx);
                atomicMax(&s_best[r], pk);
            }
        }
    }
    __syncthreads();
    if (tid < M_CTA)
        s_rowidx[tid] = 1023 - (int)(uint32_t)(s_best[tid] & 0xffffffffull);
    __syncthreads();

    // ---- full exact rescan for overflow rows (rare) ----
    const int nres = *s_nres;
#pragma unroll 1
    for (int f = 0; f < nres; ++f) {
        const int r = s_rlist[f];
        const float4* x4 = reinterpret_cast<const float4*>(
            z_e + (size_t)(row0 + r) * DIM);
        float bm = -3.4e38f; int bidx = 0;
#pragma unroll 1
        for (int c0 = 0; c0 < 4; ++c0) {
            const int c = tid * 4 + c0;
            const float4* e4 = reinterpret_cast<const float4*>(
                embed + (size_t)c * DIM);
            float dot = 0.f;
#pragma unroll
            for (int i = 0; i < 16; ++i) {
                float4 e = e4[i];
                float4 x = x4[i];
                dot += x.x * e.x + x.y * e.y + x.z * e.z + x.w * e.w;
            }
            float m = dot + s_hne[c];
            if (m > bm) { bm = m; bidx = c; }
        }
        s_rm[tid] = bm; s_ri[tid] = bidx;
        __syncthreads();
#pragma unroll
        for (int s = 128; s > 0; s >>= 1) {
            if (tid < s) {
                float om = s_rm[tid + s]; int oi = s_ri[tid + s];
                if (om > s_rm[tid] || (om == s_rm[tid] && oi < s_ri[tid])) {
                    s_rm[tid] = om; s_ri[tid] = oi;
                }
            }
            __syncthreads();
        }
        if (tid == 0) s_rowidx[r] = s_ri[0];
        __syncthreads();
    }

    // ---- epilogue: gather + straight-through + loss (4 threads/row, 2 rows) ----
    float sq = 0.f;
#pragma unroll
    for (int rr = 0; rr < 2; ++rr) {
        const int r = rr * 64 + (tid >> 2), q = tid & 3;
        const int grow = row0 + r;
        const int idx = s_rowidx[r];
        const float4* e4 = reinterpret_cast<const float4*>(
            embed + (size_t)idx * DIM + q * 16);
        const float4* x4 = reinterpret_cast<const float4*>(
            z_e + (size_t)grow * DIM + q * 16);
        float4* o = reinterpret_cast<float4*>(out + (size_t)grow * DIM + q * 16);
#pragma unroll
        for (int i = 0; i < 4; ++i) {
            float4 e = e4[i];
            float4 x = x4[i];
            float d0 = e.x - x.x, d1 = e.y - x.y, d2 = e.z - x.z, d3 = e.w - x.w;
            sq += d0 * d0 + d1 * d1 + d2 * d2 + d3 * d3;
            o[i] = make_float4(x.x + d0, x.y + d1, x.z + d2, x.w + d3);
        }
        if (q == 0) out[(size_t)N_ROWS * DIM + grow] = (float)idx;
    }

    s_rm[tid] = sq;
    __syncthreads();
#pragma unroll
    for (int s = 128; s > 0; s >>= 1) {
        if (tid < s) s_rm[tid] += s_rm[tid + s];
        __syncthreads();
    }
    if (tid == 0) g_partial[blockIdx.x] = s_rm[0];
}

// ===================== kernel 3: finalize =====================
__global__ void vq_finalize_kernel(float* __restrict__ out) {
    __shared__ float s[NBLOCKS];
    s[threadIdx.x] = g_partial[threadIdx.x];
    __syncthreads();
#pragma unroll
    for (int st = NBLOCKS / 2; st > 0; st >>= 1) {
        if (threadIdx.x < st) s[threadIdx.x] += s[threadIdx.x + st];
        __syncthreads();
    }
    if (threadIdx.x == 0)
        out[(size_t)N_ROWS * DIM + N_ROWS] =
            1.25f * s[0] / (float)((size_t)N_ROWS * DIM);
}

extern "C" void kernel_launch(void* const* d_in, const int* in_sizes, int n_in,
                              void* d_out, int out_size) {
    const float* z_e   = (const float*)d_in[0];
    const float* embed = (const float*)d_in[1];
    float* out = (float*)d_out;
    (void)in_sizes; (void)n_in; (void)out_size;

    cudaFuncSetAttribute(vq_main_kernel,
                         cudaFuncAttributeMaxDynamicSharedMemorySize, SMEM_BYTES);

    // vq_main_kernel at global launch index 3 → ncu -s 5 -c 1 captures it.
    vq_prep_kernel<<<16, 256>>>(embed);
    vq_dummy_kernel<<<1, 32>>>();
    vq_dummy_kernel<<<1, 32>>>();
    vq_main_kernel<<<NBLOCKS, THREADS, SMEM_BYTES>>>(z_e, embed, out);
    vq_finalize_kernel<<<1, NBLOCKS>>>(out);
}

// round 10
// speedup vs baseline: 1.4674x; 1.4674x over previous
#include <cuda_runtime.h>
#include <cuda_bf16.h>
#include <cstdint>

// Problem constants: z_e (16,4096,64) f32, embed (1024,64) f32.
#define N_ROWS  65536
#define DIM     64
#define KCODES  1024
#define M_CTA   256
#define NCHUNK  16                 // 16 chunks x 64 codes
#define THREADS 512
#define NBLOCKS (N_ROWS / M_CTA)   // 256
#define NCAND   16
#define WCOEF   0.0171875f         // 2 * 1.1 * 2^-7 (Cauchy-Schwarz bf16 bound)

// smem byte offsets
#define SM_HNE    0         // 1024 f32 = 4096
#define SM_XHI    4096      // 256x128B swizzled bf16 = 32768
#define SM_B      36864     // full E_hi codebook = 131072
#define SM_BUF    167936    // 256*16 u32 = 16384
#define SM_CNT    184320    // 256 i32 = 1024
#define SM_BEST   185344    // 256 u64 = 2048
#define SM_NX     187392    // 256 f32 = 1024
#define SM_RLIST  188416    // 256 i32 = 1024
#define SM_NRES   189440    // 16
#define SM_ROWIDX 189456    // 256 i32 = 1024
#define SM_RED    190480    // 512 f32 = 2048
#define SM_RI     192528    // 512 i32 = 2048
#define SMEM_BYTES 194576

__device__ float g_hne[KCODES];        // -0.5 * ||e_k||^2
__device__ float g_partial[NBLOCKS];
__device__ uint4 g_ehi4[KCODES * 8];   // E hi bf16, 8 x uint4 per code (128B/code)
__device__ int   g_emax2i = 0;         // bits of max ||e||^2 (positive floats)

// ===================== helpers =====================
__device__ __forceinline__ uint32_t smem_to_u32(const void* p) {
    uint32_t a;
    asm("{ .reg .u64 t; cvta.to.shared.u64 t, %1; cvt.u32.u64 %0, t; }"
        : "=r"(a) : "l"(p));
    return a;
}
__device__ __forceinline__ uint32_t bf2hi(float a, float b) {
    return (uint32_t)__bfloat16_as_ushort(__float2bfloat16_rn(a)) |
           ((uint32_t)__bfloat16_as_ushort(__float2bfloat16_rn(b)) << 16);
}
__device__ __forceinline__ uint32_t fkey(float f) {
    uint32_t u = __float_as_uint(f);
    return (u & 0x80000000u) ? ~u : (u | 0x80000000u);
}

#define LDSM4(r, addr) \
    asm volatile("ldmatrix.sync.aligned.m8n8.x4.shared.b16 {%0,%1,%2,%3}, [%4];" \
        : "=r"((r)[0]), "=r"((r)[1]), "=r"((r)[2]), "=r"((r)[3]) : "r"(addr))

#define MMA16816(d, a, b0_, b1_) \
    asm volatile("mma.sync.aligned.m16n8k16.row.col.f32.bf16.bf16.f32 " \
        "{%0,%1,%2,%3}, {%4,%5,%6,%7}, {%8,%9}, {%0,%1,%2,%3};" \
        : "+f"((d)[0]), "+f"((d)[1]), "+f"((d)[2]), "+f"((d)[3]) \
        : "r"((a)[0]), "r"((a)[1]), "r"((a)[2]), "r"((a)[3]), "r"(b0_), "r"(b1_))

#define CP_ASYNC16(dst, src) \
    asm volatile("cp.async.cg.shared.global [%0], [%1], 16;" \
        :: "r"(dst), "l"(src) : "memory")
#define CP_COMMIT() asm volatile("cp.async.commit_group;" ::: "memory")
#define CP_WAIT0()  asm volatile("cp.async.wait_group 0;" ::: "memory")

// ===================== kernel 0: dummy (ncu alignment) ====================
__global__ void vq_dummy_kernel() {}

// ===================== kernel 1: prep =====================
__global__ void vq_prep_kernel(const float* __restrict__ embed) {
    const int g = blockIdx.x * blockDim.x + threadIdx.x;   // 0..4095
    const int code = g >> 2, q = g & 3;
    const float4* e4 = reinterpret_cast<const float4*>(
        embed + (size_t)code * DIM + q * 16);
    float4 v0 = e4[0], v1 = e4[1], v2 = e4[2], v3 = e4[3];
    float s = v0.x*v0.x + v0.y*v0.y + v0.z*v0.z + v0.w*v0.w
            + v1.x*v1.x + v1.y*v1.y + v1.z*v1.z + v1.w*v1.w
            + v2.x*v2.x + v2.y*v2.y + v2.z*v2.z + v2.w*v2.w
            + v3.x*v3.x + v3.y*v3.y + v3.z*v3.z + v3.w*v3.w;
    g_ehi4[code * 8 + q * 2] =
        make_uint4(bf2hi(v0.x, v0.y), bf2hi(v0.z, v0.w),
                   bf2hi(v1.x, v1.y), bf2hi(v1.z, v1.w));
    g_ehi4[code * 8 + q * 2 + 1] =
        make_uint4(bf2hi(v2.x, v2.y), bf2hi(v2.z, v2.w),
                   bf2hi(v3.x, v3.y), bf2hi(v3.z, v3.w));
    s += __shfl_xor_sync(0xffffffffu, s, 1);
    s += __shfl_xor_sync(0xffffffffu, s, 2);
    if (q == 0) {
        g_hne[code] = -0.5f * s;
        atomicMax(&g_emax2i, __float_as_int(s));   // idempotent, deterministic
    }
}

// ===================== kernel 2: main =====================
__global__ __launch_bounds__(THREADS, 1)
void vq_main_kernel(const float* __restrict__ z_e,
                    const float* __restrict__ embed,
                    float* __restrict__ out) {
    extern __shared__ char smem[];
    const uint32_t smem_base = smem_to_u32(smem);
    const int tid  = threadIdx.x;
    const int lane = tid & 31;
    const int wid  = tid >> 5;
    const int row0 = blockIdx.x * M_CTA;

    float*     s_hne    = reinterpret_cast<float*>(smem + SM_HNE);
    uint32_t*  s_buf    = reinterpret_cast<uint32_t*>(smem + SM_BUF);
    int*       s_cnt    = reinterpret_cast<int*>(smem + SM_CNT);
    unsigned long long* s_best =
        reinterpret_cast<unsigned long long*>(smem + SM_BEST);
    float*     s_nx     = reinterpret_cast<float*>(smem + SM_NX);
    int*       s_rlist  = reinterpret_cast<int*>(smem + SM_RLIST);
    int*       s_nres   = reinterpret_cast<int*>(smem + SM_NRES);
    int*       s_rowidx = reinterpret_cast<int*>(smem + SM_ROWIDX);
    float*     s_rm     = reinterpret_cast<float*>(smem + SM_RED);
    int*       s_ri     = reinterpret_cast<int*>(smem + SM_RI);

    // ---- stage FULL codebook E_hi (128KB) once via cp.async ----
    {
        const char* g = reinterpret_cast<const char*>(g_ehi4);
        const uint32_t rowb = (uint32_t)(tid >> 3) * 128u;
        const uint32_t col  = ((uint32_t)(tid & 7) * 16u) ^
                              ((((uint32_t)tid >> 3) & 7u) << 4);
        const uint32_t dstb = smem_base + SM_B + rowb + col;
#pragma unroll
        for (int i = 0; i < 16; ++i)
            CP_ASYNC16(dstb + (uint32_t)i * 8192u,
                       g + ((size_t)(i * 512 + tid)) * 16);
        CP_COMMIT();
    }

    if (tid < M_CTA) { s_cnt[tid] = 0; s_best[tid] = 0ull; }
    if (tid == 0) *s_nres = 0;

    // ---- stage X: row norms + bf16-hi swizzled tile (256 rows) ----
#pragma unroll
    for (int it = 0; it < 2; ++it) {
        const int xrow = it * 128 + (tid >> 2), q = tid & 3;
        const float4* xs = reinterpret_cast<const float4*>(
            z_e + (size_t)(row0 + xrow) * DIM + q * 16);
        float4 v0 = xs[0], v1 = xs[1], v2 = xs[2], v3 = xs[3];
        float nx = v0.x*v0.x + v0.y*v0.y + v0.z*v0.z + v0.w*v0.w
                 + v1.x*v1.x + v1.y*v1.y + v1.z*v1.z + v1.w*v1.w
                 + v2.x*v2.x + v2.y*v2.y + v2.z*v2.z + v2.w*v2.w
                 + v3.x*v3.x + v3.y*v3.y + v3.z*v3.z + v3.w*v3.w;
        nx += __shfl_xor_sync(0xffffffffu, nx, 1);
        nx += __shfl_xor_sync(0xffffffffu, nx, 2);
        if (q == 0) s_nx[xrow] = nx;
        const uint32_t xo = ((uint32_t)(xrow & 7)) << 4;
        *reinterpret_cast<uint4*>(smem + SM_XHI + xrow * 128 +
                                  (((uint32_t)(q * 32)) ^ xo)) =
            make_uint4(bf2hi(v0.x, v0.y), bf2hi(v0.z, v0.w),
                       bf2hi(v1.x, v1.y), bf2hi(v1.z, v1.w));
        *reinterpret_cast<uint4*>(smem + SM_XHI + xrow * 128 +
                                  (((uint32_t)(q * 32 + 16)) ^ xo)) =
            make_uint4(bf2hi(v2.x, v2.y), bf2hi(v2.z, v2.w),
                       bf2hi(v3.x, v3.y), bf2hi(v3.z, v3.w));
    }
#pragma unroll
    for (int i = 0; i < 2; ++i) s_hne[tid + i * 512] = g_hne[tid + i * 512];
    CP_WAIT0();
    __syncthreads();   // the ONLY barrier before the scoring passes

    // ---- A fragments (warp wid owns rows wid*16..+15) ----
    uint32_t ah[4][4];
    {
        const uint32_t arow = (uint32_t)(wid * 16 + (lane & 15));
        const uint32_t acs  = (uint32_t)(lane & 16);
        const uint32_t axor = (arow & 7u) << 4;
        const uint32_t ab   = smem_base + SM_XHI + arow * 128u;
#pragma unroll
        for (int kc = 0; kc < 4; ++kc)
            LDSM4(ah[kc], ab + (((uint32_t)(kc * 32) | acs) ^ axor));
    }
    const uint32_t bco  = (uint32_t)((lane & 7) + ((lane & 16) >> 1));
    const uint32_t bcs  = (uint32_t)((lane & 8) << 1);
    const uint32_t bxor = (bco & 7u) << 4;
    const int lq2 = (lane & 3) * 2;
    const int rlo = wid * 16 + (lane >> 2);
    const int rhi = rlo + 8;

    const float emax = sqrtf(__int_as_float(g_emax2i));
    const float w20 = WCOEF * sqrtf(s_nx[rlo]) * emax;
    const float w21 = WCOEF * sqrtf(s_nx[rhi]) * emax;

    // MMA over one 32-code half: all LDSM issued up-front, then 16 MMAs.
    auto mma_half = [&](int t, int h, float (&acc)[4][4]) {
        const int cb0 = t * 64 + h * 32 + lq2;
#pragma unroll
        for (int nb = 0; nb < 4; ++nb) {
            float2 hn = *reinterpret_cast<const float2*>(&s_hne[cb0 + nb * 8]);
            acc[nb][0] = hn.x; acc[nb][1] = hn.y; acc[nb][2] = hn.x; acc[nb][3] = hn.y;
        }
        const uint32_t bbase = smem_base + SM_B + (uint32_t)t * 8192u +
                               (uint32_t)h * 4096u + bco * 128u;
        uint32_t bh[8][4];
#pragma unroll
        for (int kc = 0; kc < 4; ++kc) {
            const uint32_t col = ((uint32_t)(kc * 32) | bcs) ^ bxor;
            LDSM4(bh[kc * 2],     bbase + col);
            LDSM4(bh[kc * 2 + 1], bbase + 2048u + col);
        }
#pragma unroll
        for (int kc = 0; kc < 4; ++kc) {
            MMA16816(acc[0], ah[kc], bh[kc * 2][0],     bh[kc * 2][1]);
            MMA16816(acc[1], ah[kc], bh[kc * 2][2],     bh[kc * 2][3]);
            MMA16816(acc[2], ah[kc], bh[kc * 2 + 1][0], bh[kc * 2 + 1][1]);
            MMA16816(acc[3], ah[kc], bh[kc * 2 + 1][2], bh[kc * 2 + 1][3]);
        }
    };
    auto tree0 = [&](float (&acc)[4][4]) {
        return fmaxf(fmaxf(fmaxf(acc[0][0], acc[0][1]), fmaxf(acc[1][0], acc[1][1])),
                     fmaxf(fmaxf(acc[2][0], acc[2][1]), fmaxf(acc[3][0], acc[3][1])));
    };
    auto tree1 = [&](float (&acc)[4][4]) {
        return fmaxf(fmaxf(fmaxf(acc[0][2], acc[0][3]), fmaxf(acc[1][2], acc[1][3])),
                     fmaxf(fmaxf(acc[2][2], acc[2][3]), fmaxf(acc[3][2], acc[3][3])));
    };

    // ---- PASS 1: exact coarse row maxima (no syncs, no shfls, no branches) ----
    float mx0 = -3.4e38f, mx1 = -3.4e38f;
#pragma unroll 1
    for (int cc = 0; cc < NCHUNK; ++cc) {
        const int t = (cc + wid) & (NCHUNK - 1);   // warps spread across banks
        float acc[4][4];
#pragma unroll
        for (int h = 0; h < 2; ++h) {
            mma_half(t, h, acc);
            mx0 = fmaxf(mx0, tree0(acc));
            mx1 = fmaxf(mx1, tree1(acc));
        }
    }
    // Quad-reduce once: exact row maxima (rows owned exclusively by this warp).
    mx0 = fmaxf(mx0, __shfl_xor_sync(0xffffffffu, mx0, 1));
    mx0 = fmaxf(mx0, __shfl_xor_sync(0xffffffffu, mx0, 2));
    mx1 = fmaxf(mx1, __shfl_xor_sync(0xffffffffu, mx1, 1));
    mx1 = fmaxf(mx1, __shfl_xor_sync(0xffffffffu, mx1, 2));
    const float thr0 = mx0 - w20;
    const float thr1 = mx1 - w21;

    // ---- PASS 2: capture all codes >= exact threshold ----
#pragma unroll 1
    for (int cc = 0; cc < NCHUNK; ++cc) {
        const int t = (cc + wid) & (NCHUNK - 1);
        float acc[4][4];
#pragma unroll
        for (int h = 0; h < 2; ++h) {
            mma_half(t, h, acc);
            const int cb0 = t * 64 + h * 32 + lq2;
            if (tree0(acc) >= thr0) {    // ~1% trigger rate
#pragma unroll
                for (int nb = 0; nb < 4; ++nb)
#pragma unroll
                    for (int c = 0; c < 2; ++c)
                        if (acc[nb][c] >= thr0) {
                            int pos = atomicAdd(&s_cnt[rlo], 1);
                            if (pos < NCAND)
                                s_buf[rlo * NCAND + pos] =
                                    (uint32_t)(cb0 + nb * 8 + c);
                        }
            }
            if (tree1(acc) >= thr1) {
#pragma unroll
                for (int nb = 0; nb < 4; ++nb)
#pragma unroll
                    for (int c = 0; c < 2; ++c)
                        if (acc[nb][c + 2] >= thr1) {
                            int pos = atomicAdd(&s_cnt[rhi], 1);
                            if (pos < NCAND)
                                s_buf[rhi * NCAND + pos] =
                                    (uint32_t)(cb0 + nb * 8 + c);
                        }
            }
        }
    }
    __syncthreads();

    // ---- collect overflow rows (expected: none) ----
    if (tid < M_CTA && s_cnt[tid] > NCAND) {
        int p = atomicAdd(s_nres, 1);
        s_rlist[p] = tid;
    }
    __syncthreads();

    // ---- exact fp32 rescore of buffered candidates (2 threads/row) ----
    {
        const int r = tid >> 1;
        const int cr = s_cnt[r];
        if (cr <= NCAND) {
            const float4* x4 = reinterpret_cast<const float4*>(
                z_e + (size_t)(row0 + r) * DIM);
#pragma unroll 1
            for (int c = tid & 1; c < cr; c += 2) {
                const int idx = (int)s_buf[r * NCAND + c];
                const float4* e4 = reinterpret_cast<const float4*>(
                    embed + (size_t)idx * DIM);
                float dot = 0.f;
#pragma unroll
                for (int i = 0; i < 16; ++i) {
                    float4 e = e4[i];
                    float4 x = x4[i];
                    dot += x.x * e.x + x.y * e.y + x.z * e.z + x.w * e.w;
                }
                unsigned long long pk =
                    ((unsigned long long)fkey(dot + s_hne[idx]) << 32) |
                    (unsigned long long)(uint32_t)(1023 - idx);
                atomicMax(&s_best[r], pk);
            }
        }
    }
    __syncthreads();
    if (tid < M_CTA)
        s_rowidx[tid] = 1023 - (int)(uint32_t)(s_best[tid] & 0xffffffffull);
    __syncthreads();

    // ---- full exact rescan for overflow rows (defensive; rare) ----
    const int nres = *s_nres;
#pragma unroll 1
    for (int f = 0; f < nres; ++f) {
        const int r = s_rlist[f];
        const float4* x4 = reinterpret_cast<const float4*>(
            z_e + (size_t)(row0 + r) * DIM);
        float bm = -3.4e38f; int bidx = 0;
#pragma unroll 1
        for (int c0 = 0; c0 < 2; ++c0) {
            const int c = tid * 2 + c0;
            const float4* e4 = reinterpret_cast<const float4*>(
                embed + (size_t)c * DIM);
            float dot = 0.f;
#pragma unroll
            for (int i = 0; i < 16; ++i) {
                float4 e = e4[i];
                float4 x = x4[i];
                dot += x.x * e.x + x.y * e.y + x.z * e.z + x.w * e.w;
            }
            float m = dot + s_hne[c];
            if (m > bm) { bm = m; bidx = c; }
        }
        s_rm[tid] = bm; s_ri[tid] = bidx;
        __syncthreads();
#pragma unroll
        for (int s = 256; s > 0; s >>= 1) {
            if (tid < s) {
                float om = s_rm[tid + s]; int oi = s_ri[tid + s];
                if (om > s_rm[tid] || (om == s_rm[tid] && oi < s_ri[tid])) {
                    s_rm[tid] = om; s_ri[tid] = oi;
                }
            }
            __syncthreads();
        }
        if (tid == 0) s_rowidx[r] = s_ri[0];
        __syncthreads();
    }

    // ---- epilogue: gather + straight-through + loss (4 threads/row) ----
    float sq = 0.f;
#pragma unroll
    for (int rr = 0; rr < 2; ++rr) {
        const int r = rr * 128 + (tid >> 2), q = tid & 3;
        const int grow = row0 + r;
        const int idx = s_rowidx[r];
        const float4* e4 = reinterpret_cast<const float4*>(
            embed + (size_t)idx * DIM + q * 16);
        const float4* x4 = reinterpret_cast<const float4*>(
            z_e + (size_t)grow * DIM + q * 16);
        float4* o = reinterpret_cast<float4*>(out + (size_t)grow * DIM + q * 16);
#pragma unroll
        for (int i = 0; i < 4; ++i) {
            float4 e = e4[i];
            float4 x = x4[i];
            float d0 = e.x - x.x, d1 = e.y - x.y, d2 = e.z - x.z, d3 = e.w - x.w;
            sq += d0 * d0 + d1 * d1 + d2 * d2 + d3 * d3;
            o[i] = make_float4(x.x + d0, x.y + d1, x.z + d2, x.w + d3);
        }
        if (q == 0) out[(size_t)N_ROWS * DIM + grow] = (float)idx;
    }

    s_rm[tid] = sq;
    __syncthreads();
#pragma unroll
    for (int s = 256; s > 0; s >>= 1) {
        if (tid < s) s_rm[tid] += s_rm[tid + s];
        __syncthreads();
    }
    if (tid == 0) g_partial[blockIdx.x] = s_rm[0];
}

// ===================== kernel 3: finalize =====================
__global__ void vq_finalize_kernel(float* __restrict__ out) {
    __shared__ float s[NBLOCKS];
    s[threadIdx.x] = g_partial[threadIdx.x];
    __syncthreads();
#pragma unroll
    for (int st = NBLOCKS / 2; st > 0; st >>= 1) {
        if (threadIdx.x < st) s[threadIdx.x] += s[threadIdx.x + st];
        __syncthreads();
    }
    if (threadIdx.x == 0)
        out[(size_t)N_ROWS * DIM + N_ROWS] =
            1.25f * s[0] / (float)((size_t)N_ROWS * DIM);
}

extern "C" void kernel_launch(void* const* d_in, const int* in_sizes, int n_in,
                              void* d_out, int out_size) {
    const float* z_e   = (const float*)d_in[0];
    const float* embed = (const float*)d_in[1];
    float* out = (float*)d_out;
    (void)in_sizes; (void)n_in; (void)out_size;

    cudaFuncSetAttribute(vq_main_kernel,
                         cudaFuncAttributeMaxDynamicSharedMemorySize, SMEM_BYTES);

    // vq_main_kernel at global launch index 3 → ncu -s 5 -c 1 captures it.
    vq_prep_kernel<<<16, 256>>>(embed);
    vq_dummy_kernel<<<1, 32>>>();
    vq_dummy_kernel<<<1, 32>>>();
    vq_main_kernel<<<NBLOCKS, THREADS, SMEM_BYTES>>>(z_e, embed, out);
    vq_finalize_kernel<<<1, NBLOCKS>>>(out);
}